// round 1
// baseline (speedup 1.0000x reference)
#include <cuda_runtime.h>
#include <math.h>

#define BATCH 4
#define SEQ   2048
#define HDIM  1024
#define EDIM  1024

// Scratch (device globals are the sanctioned scratch mechanism)
__device__ float g_q[(size_t)BATCH * SEQ * EDIM];           // 32 MB
__device__ float g_k[(size_t)BATCH * SEQ * EDIM];           // 32 MB
__device__ float g_v[(size_t)BATCH * SEQ * EDIM];           // 32 MB
__device__ float g_p[(size_t)BATCH * SEQ * SEQ];            // 64 MB

// ---------------------------------------------------------------------------
// 128x128x8 SGEMM tile body, 256 threads, 8x8 accumulators per thread.
// K-major variant: C[m,n] = scale * sum_k A[m,k] * B[n,k]  (+bias[n])
// ---------------------------------------------------------------------------
__device__ __forceinline__ void gemm_kmajor_body(
    const float* __restrict__ A, int lda,
    const float* __restrict__ B, int ldb,
    float*       __restrict__ C, int ldc,
    const float* __restrict__ bias,
    float scale, int K, int m0, int n0)
{
    __shared__ float As[128][8];
    __shared__ float Bs[8][132];   // padded row so k and k+4 stores hit disjoint banks

    const int tid = threadIdx.x;
    const int tx  = tid & 15;      // column group (0..15)
    const int ty  = tid >> 4;      // row group    (0..15)

    float acc[8][8];
    #pragma unroll
    for (int i = 0; i < 8; i++)
        #pragma unroll
        for (int j = 0; j < 8; j++) acc[i][j] = 0.f;

    const int la_m = tid >> 1;           // 0..127
    const int la_k = (tid & 1) * 4;      // 0 or 4
    const float* Aptr = A + (size_t)(m0 + la_m) * lda + la_k;
    const float* Bptr = B + (size_t)(n0 + la_m) * ldb + la_k;

    for (int kt = 0; kt < K; kt += 8) {
        float4 av = *(const float4*)(Aptr + kt);
        float4 bv = *(const float4*)(Bptr + kt);
        *(float4*)&As[la_m][la_k] = av;
        Bs[la_k + 0][la_m] = bv.x;
        Bs[la_k + 1][la_m] = bv.y;
        Bs[la_k + 2][la_m] = bv.z;
        Bs[la_k + 3][la_m] = bv.w;
        __syncthreads();

        #pragma unroll
        for (int kk = 0; kk < 8; kk++) {
            float a[8], b[8];
            #pragma unroll
            for (int i = 0; i < 8; i++) a[i] = As[ty * 8 + i][kk];
            float4 b0 = *(const float4*)&Bs[kk][tx * 8];
            float4 b1 = *(const float4*)&Bs[kk][tx * 8 + 4];
            b[0]=b0.x; b[1]=b0.y; b[2]=b0.z; b[3]=b0.w;
            b[4]=b1.x; b[5]=b1.y; b[6]=b1.z; b[7]=b1.w;
            #pragma unroll
            for (int i = 0; i < 8; i++)
                #pragma unroll
                for (int j = 0; j < 8; j++)
                    acc[i][j] = fmaf(a[i], b[j], acc[i][j]);
        }
        __syncthreads();
    }

    #pragma unroll
    for (int i = 0; i < 8; i++) {
        const int m = m0 + ty * 8 + i;
        float* crow = C + (size_t)m * ldc + n0 + tx * 8;
        float r[8];
        #pragma unroll
        for (int j = 0; j < 8; j++) {
            float v = acc[i][j] * scale;
            if (bias) v += bias[n0 + tx * 8 + j];
            r[j] = v;
        }
        *(float4*)&crow[0] = make_float4(r[0], r[1], r[2], r[3]);
        *(float4*)&crow[4] = make_float4(r[4], r[5], r[6], r[7]);
    }
}

// N-major B variant: C[m,n] = sum_k A[m,k] * B[k,n]
__device__ __forceinline__ void gemm_nmajor_body(
    const float* __restrict__ A, int lda,    // A[m][k], k contiguous
    const float* __restrict__ B, int ldb,    // B[k][n], n contiguous
    float*       __restrict__ C, int ldc,
    int K, int m0, int n0)
{
    __shared__ float As[128][8];
    __shared__ float Bs[8][132];

    const int tid = threadIdx.x;
    const int tx  = tid & 15;
    const int ty  = tid >> 4;

    float acc[8][8];
    #pragma unroll
    for (int i = 0; i < 8; i++)
        #pragma unroll
        for (int j = 0; j < 8; j++) acc[i][j] = 0.f;

    const int la_m = tid >> 1;
    const int la_k = (tid & 1) * 4;
    const int lb_k = tid >> 5;           // 0..7
    const int lb_n = (tid & 31) * 4;     // 0..124
    const float* Aptr = A + (size_t)(m0 + la_m) * lda + la_k;
    const float* Bptr = B + (size_t)lb_k * ldb + n0 + lb_n;

    for (int kt = 0; kt < K; kt += 8) {
        float4 av = *(const float4*)(Aptr + kt);
        float4 bv = *(const float4*)(Bptr + (size_t)kt * ldb);
        *(float4*)&As[la_m][la_k] = av;
        *(float4*)&Bs[lb_k][lb_n] = bv;
        __syncthreads();

        #pragma unroll
        for (int kk = 0; kk < 8; kk++) {
            float a[8], b[8];
            #pragma unroll
            for (int i = 0; i < 8; i++) a[i] = As[ty * 8 + i][kk];
            float4 b0 = *(const float4*)&Bs[kk][tx * 8];
            float4 b1 = *(const float4*)&Bs[kk][tx * 8 + 4];
            b[0]=b0.x; b[1]=b0.y; b[2]=b0.z; b[3]=b0.w;
            b[4]=b1.x; b[5]=b1.y; b[6]=b1.z; b[7]=b1.w;
            #pragma unroll
            for (int i = 0; i < 8; i++)
                #pragma unroll
                for (int j = 0; j < 8; j++)
                    acc[i][j] = fmaf(a[i], b[j], acc[i][j]);
        }
        __syncthreads();
    }

    #pragma unroll
    for (int i = 0; i < 8; i++) {
        const int m = m0 + ty * 8 + i;
        float* crow = C + (size_t)m * ldc + n0 + tx * 8;
        *(float4*)&crow[0] = make_float4(acc[i][0], acc[i][1], acc[i][2], acc[i][3]);
        *(float4*)&crow[4] = make_float4(acc[i][4], acc[i][5], acc[i][6], acc[i][7]);
    }
}

// ---------------------------------------------------------------------------
// Kernel 1: fused QKV projections. grid (E/128, M/128, 3)
// out[m,e] = xs[m,:] . W[e,:] + b[e]   (M = B*S = 8192, K = HDIM)
// ---------------------------------------------------------------------------
__global__ __launch_bounds__(256) void qkv_proj_kernel(
    const float* __restrict__ xs,
    const float* __restrict__ wq, const float* __restrict__ bq,
    const float* __restrict__ wk, const float* __restrict__ bk,
    const float* __restrict__ wv, const float* __restrict__ bv)
{
    const float* w; const float* bias; float* out;
    if      (blockIdx.z == 0) { w = wq; bias = bq; out = g_q; }
    else if (blockIdx.z == 1) { w = wk; bias = bk; out = g_k; }
    else                      { w = wv; bias = bv; out = g_v; }
    gemm_kmajor_body(xs, HDIM, w, HDIM, out, EDIM, bias, 1.0f, HDIM,
                     blockIdx.y * 128, blockIdx.x * 128);
}

// ---------------------------------------------------------------------------
// Kernel 2: causal scores. grid (S/128, S/128, B). Upper-triangle blocks skip.
// p[b,m,n] = (q[b,m,:] . k[b,n,:]) / 32
// ---------------------------------------------------------------------------
__global__ __launch_bounds__(256) void qk_kernel()
{
    if (blockIdx.x > blockIdx.y) return;   // strictly above-diagonal: never read
    const int b = blockIdx.z;
    gemm_kmajor_body(g_q + (size_t)b * SEQ * EDIM, EDIM,
                     g_k + (size_t)b * SEQ * EDIM, EDIM,
                     g_p + (size_t)b * SEQ * SEQ,  SEQ,
                     nullptr, 0.03125f /* 1/sqrt(1024) */, EDIM,
                     blockIdx.y * 128, blockIdx.x * 128);
}

// ---------------------------------------------------------------------------
// Kernel 3: in-place causal row softmax. grid (S, B), 256 threads.
// Writes the FULL row: probs for n<=m, explicit 0 for n>m (so PV needs no mask).
// ---------------------------------------------------------------------------
__global__ __launch_bounds__(256) void softmax_kernel()
{
    const int m = blockIdx.x, b = blockIdx.y;
    float* row = g_p + (size_t)b * SEQ * SEQ + (size_t)m * SEQ;
    const int nv = m + 1;
    const int tid = threadIdx.x;
    __shared__ float red[8];

    float mx = -3.4e38f;
    for (int n = tid; n < nv; n += 256) mx = fmaxf(mx, row[n]);
    #pragma unroll
    for (int o = 16; o; o >>= 1) mx = fmaxf(mx, __shfl_xor_sync(0xffffffffu, mx, o));
    if ((tid & 31) == 0) red[tid >> 5] = mx;
    __syncthreads();
    float mall = red[0];
    #pragma unroll
    for (int i = 1; i < 8; i++) mall = fmaxf(mall, red[i]);
    __syncthreads();

    float s = 0.f;
    for (int n = tid; n < nv; n += 256) s += __expf(row[n] - mall);
    #pragma unroll
    for (int o = 16; o; o >>= 1) s += __shfl_xor_sync(0xffffffffu, s, o);
    if ((tid & 31) == 0) red[tid >> 5] = s;
    __syncthreads();
    float tot = 0.f;
    #pragma unroll
    for (int i = 0; i < 8; i++) tot += red[i];
    const float inv = 1.0f / tot;

    for (int n = tid; n < SEQ; n += 256)
        row[n] = (n < nv) ? __expf(row[n] - mall) * inv : 0.f;
}

// ---------------------------------------------------------------------------
// Kernel 4: y = P @ V. grid (E/128, S/128, B). K loop bounded at the diagonal.
// ---------------------------------------------------------------------------
__global__ __launch_bounds__(256) void pv_kernel(float* __restrict__ out)
{
    const int b = blockIdx.z;
    const int Kloop = (blockIdx.y + 1) * 128;   // columns n < m_tile_end suffice
    gemm_nmajor_body(g_p + (size_t)b * SEQ * SEQ, SEQ,
                     g_v + (size_t)b * SEQ * EDIM, EDIM,
                     out + (size_t)b * SEQ * EDIM, EDIM,
                     Kloop, blockIdx.y * 128, blockIdx.x * 128);
}

// ---------------------------------------------------------------------------
extern "C" void kernel_launch(void* const* d_in, const int* in_sizes, int n_in,
                              void* d_out, int out_size)
{
    const float* xs   = (const float*)d_in[0];
    const float* WQ_w = (const float*)d_in[1];
    const float* WQ_b = (const float*)d_in[2];
    const float* WK_w = (const float*)d_in[3];
    const float* WK_b = (const float*)d_in[4];
    const float* WV_w = (const float*)d_in[5];
    const float* WV_b = (const float*)d_in[6];
    float* out = (float*)d_out;

    qkv_proj_kernel<<<dim3(EDIM / 128, (BATCH * SEQ) / 128, 3), 256>>>(
        xs, WQ_w, WQ_b, WK_w, WK_b, WV_w, WV_b);
    qk_kernel<<<dim3(SEQ / 128, SEQ / 128, BATCH), 256>>>();
    softmax_kernel<<<dim3(SEQ, BATCH), 256>>>();
    pv_kernel<<<dim3(EDIM / 128, SEQ / 128, BATCH), 256>>>(out);
}

// round 3
// speedup vs baseline: 3.7213x; 3.7213x over previous
#include <cuda_runtime.h>
#include <cuda_bf16.h>
#include <stdint.h>
#include <math.h>

#define BATCH 4
#define SEQ   2048
#define HDIM  1024
#define EDIM  1024

// ---------------------------------------------------------------------------
// Scratch (device globals are the sanctioned scratch mechanism)
// ---------------------------------------------------------------------------
__device__ float g_q [(size_t)BATCH * SEQ * EDIM];          // 32 MB  [b*S+s][e]
__device__ float g_k [(size_t)BATCH * SEQ * EDIM];          // 32 MB  [b*S+s][e]
__device__ float g_vt[(size_t)EDIM * BATCH * SEQ];          // 32 MB  [e][b*S+s]
__device__ float g_p [(size_t)BATCH * SEQ * SEQ];           // 64 MB  [b][m][n]

// ---------------------------------------------------------------------------
// SMEM tile geometry: K-chunk = 32 bf16 (64 B payload) padded to 80 B rows.
// 80 B stride => ldmatrix.x4 row addresses hit disjoint bank quads (conflict-free).
// ---------------------------------------------------------------------------
#define TROW     80
#define TILE_B   (128 * TROW)          // 10240 B per 128x32 bf16 tile
#define STAGE_B  (4 * TILE_B)          // hiA, loA, hiB, loB
#define SMEM_BYTES (2 * STAGE_B)       // 81920 B double buffered

__device__ __forceinline__ uint32_t smem_u32(const void* p) {
    uint32_t a;
    asm("{ .reg .u64 t; cvta.to.shared.u64 t, %1; cvt.u32.u64 %0, t; }"
        : "=r"(a) : "l"(p));
    return a;
}

__device__ __forceinline__ void ldsm4(uint32_t* r, uint32_t addr) {
    asm volatile("ldmatrix.sync.aligned.m8n8.x4.shared.b16 {%0,%1,%2,%3}, [%4];"
                 : "=r"(r[0]), "=r"(r[1]), "=r"(r[2]), "=r"(r[3]) : "r"(addr));
}

__device__ __forceinline__ void mma16816(float* c, const uint32_t* a,
                                         uint32_t b0, uint32_t b1) {
    asm volatile(
        "mma.sync.aligned.m16n8k16.row.col.f32.bf16.bf16.f32 "
        "{%0,%1,%2,%3}, {%4,%5,%6,%7}, {%8,%9}, {%0,%1,%2,%3};"
        : "+f"(c[0]), "+f"(c[1]), "+f"(c[2]), "+f"(c[3])
        : "r"(a[0]), "r"(a[1]), "r"(a[2]), "r"(a[3]), "r"(b0), "r"(b1));
}

// Split fp32x4 -> (hi, lo) bf16x4 and store into a tile at (row, c4).
__device__ __forceinline__ void cvt_store(char* hi, char* lo, int row, int c4,
                                          float4 v) {
    __nv_bfloat162 h0 = __floats2bfloat162_rn(v.x, v.y);
    __nv_bfloat162 h1 = __floats2bfloat162_rn(v.z, v.w);
    float r0 = v.x - __low2float(h0);
    float r1 = v.y - __high2float(h0);
    float r2 = v.z - __low2float(h1);
    float r3 = v.w - __high2float(h1);
    __nv_bfloat162 l0 = __floats2bfloat162_rn(r0, r1);
    __nv_bfloat162 l1 = __floats2bfloat162_rn(r2, r3);
    uint32_t off = (uint32_t)(row * TROW + c4 * 8);
    uint2 uh, ul;
    uh.x = *(uint32_t*)&h0; uh.y = *(uint32_t*)&h1;
    ul.x = *(uint32_t*)&l0; ul.y = *(uint32_t*)&l1;
    *(uint2*)(hi + off) = uh;
    *(uint2*)(lo + off) = ul;
}

// ---------------------------------------------------------------------------
// 128x128 GEMM tile via mma.sync bf16 split emulation.
// C[m,n] = scale * sum_k A[m,k]*B[n,k] (+bias). K = nchunks * 32.
// bias_mode: 0 none, 1 column bias bias[n], 2 row bias bias[m].
// 256 threads (8 warps: warp_m = w>>1 in 0..3, warp_n = w&1 in 0..1).
// ---------------------------------------------------------------------------
__device__ void gemm_mma(const float* __restrict__ A, size_t lda,
                         const float* __restrict__ B, size_t ldb,
                         float* __restrict__ C, size_t ldc,
                         const float* __restrict__ bias, int bias_mode,
                         float scale, int m0, int n0, int nchunks)
{
    extern __shared__ __align__(128) char smem[];
    const int tid  = threadIdx.x;
    const int lane = tid & 31;
    const int wid  = tid >> 5;
    const int wm   = wid >> 1;       // 0..3
    const int wn   = wid & 1;        // 0..1

    // global-load assignment: 128 rows x 8 float4-cols per operand, 4 per thread
    const int lr = tid >> 3;         // 0..31
    const int lc = tid & 7;          // 0..7

    float acc[2][8][4];
    #pragma unroll
    for (int i = 0; i < 2; i++)
        #pragma unroll
        for (int j = 0; j < 8; j++)
            #pragma unroll
            for (int q = 0; q < 4; q++) acc[i][j][q] = 0.f;

    // lane-dependent ldmatrix offsets (bytes, within a tile)
    const uint32_t a_off = (uint32_t)((wm * 32 + (lane & 15)) * TROW
                                      + ((lane >> 4) << 4));
    const uint32_t b_off = (uint32_t)((wn * 64 + (lane & 7) + ((lane >> 4) << 3)) * TROW
                                      + (((lane >> 3) & 1) << 4));

    float4 pa[4], pb[4];

    // prologue: chunk 0
    #pragma unroll
    for (int i = 0; i < 4; i++) {
        pa[i] = *(const float4*)(A + (size_t)(m0 + lr + 32 * i) * lda + lc * 4);
        pb[i] = *(const float4*)(B + (size_t)(n0 + lr + 32 * i) * ldb + lc * 4);
    }
    {
        char* st = smem;
        #pragma unroll
        for (int i = 0; i < 4; i++) {
            cvt_store(st,              st + TILE_B,     lr + 32 * i, lc, pa[i]);
            cvt_store(st + 2 * TILE_B, st + 3 * TILE_B, lr + 32 * i, lc, pb[i]);
        }
    }
    __syncthreads();

    for (int c = 0; c < nchunks; ++c) {
        if (c + 1 < nchunks) {
            const int kt = (c + 1) * 32;
            #pragma unroll
            for (int i = 0; i < 4; i++) {
                pa[i] = *(const float4*)(A + (size_t)(m0 + lr + 32 * i) * lda + kt + lc * 4);
                pb[i] = *(const float4*)(B + (size_t)(n0 + lr + 32 * i) * ldb + kt + lc * 4);
            }
        }

        char* st = smem + (c & 1) * STAGE_B;
        const uint32_t hiA = smem_u32(st);
        const uint32_t loA = hiA + TILE_B;
        const uint32_t hiB = hiA + 2 * TILE_B;
        const uint32_t loB = hiA + 3 * TILE_B;

        #pragma unroll
        for (int s = 0; s < 2; s++) {
            const uint32_t KB = s * 32;
            uint32_t ah[2][4], al[2][4], bb[4][4];
            #pragma unroll
            for (int mt = 0; mt < 2; mt++)
                ldsm4(ah[mt], hiA + a_off + mt * 16 * TROW + KB);
            #pragma unroll
            for (int mt = 0; mt < 2; mt++)
                ldsm4(al[mt], loA + a_off + mt * 16 * TROW + KB);
            #pragma unroll
            for (int p = 0; p < 4; p++)
                ldsm4(bb[p], hiB + b_off + p * 16 * TROW + KB);
            // hi*hi and lo*hi
            #pragma unroll
            for (int mt = 0; mt < 2; mt++)
                #pragma unroll
                for (int p = 0; p < 4; p++) {
                    mma16816(acc[mt][2 * p],     ah[mt], bb[p][0], bb[p][1]);
                    mma16816(acc[mt][2 * p + 1], ah[mt], bb[p][2], bb[p][3]);
                    mma16816(acc[mt][2 * p],     al[mt], bb[p][0], bb[p][1]);
                    mma16816(acc[mt][2 * p + 1], al[mt], bb[p][2], bb[p][3]);
                }
            // hi*lo
            #pragma unroll
            for (int p = 0; p < 4; p++)
                ldsm4(bb[p], loB + b_off + p * 16 * TROW + KB);
            #pragma unroll
            for (int mt = 0; mt < 2; mt++)
                #pragma unroll
                for (int p = 0; p < 4; p++) {
                    mma16816(acc[mt][2 * p],     ah[mt], bb[p][0], bb[p][1]);
                    mma16816(acc[mt][2 * p + 1], ah[mt], bb[p][2], bb[p][3]);
                }
        }

        if (c + 1 < nchunks) {
            char* nx = smem + ((c + 1) & 1) * STAGE_B;
            #pragma unroll
            for (int i = 0; i < 4; i++) {
                cvt_store(nx,              nx + TILE_B,     lr + 32 * i, lc, pa[i]);
                cvt_store(nx + 2 * TILE_B, nx + 3 * TILE_B, lr + 32 * i, lc, pb[i]);
            }
        }
        __syncthreads();
    }

    // epilogue: scatter fragments
    const int g   = lane >> 2;
    const int tig = lane & 3;
    #pragma unroll
    for (int mt = 0; mt < 2; mt++) {
        const int r0 = m0 + wm * 32 + mt * 16 + g;
        #pragma unroll
        for (int nt = 0; nt < 8; nt++) {
            const int col = n0 + wn * 64 + nt * 8 + tig * 2;
            float b0 = 0.f, b1 = 0.f;
            if (bias_mode == 1) { b0 = bias[col]; b1 = bias[col + 1]; }
            float2 v0, v1;
            v0.x = acc[mt][nt][0] * scale + b0;
            v0.y = acc[mt][nt][1] * scale + b1;
            v1.x = acc[mt][nt][2] * scale + b0;
            v1.y = acc[mt][nt][3] * scale + b1;
            if (bias_mode == 2) {
                float rb0 = bias[r0], rb1 = bias[r0 + 8];
                v0.x += rb0; v0.y += rb0;
                v1.x += rb1; v1.y += rb1;
            }
            *(float2*)(C + (size_t)r0 * ldc + col)       = v0;
            *(float2*)(C + (size_t)(r0 + 8) * ldc + col) = v1;
        }
    }
}

// ---------------------------------------------------------------------------
// GEMM wrappers
// ---------------------------------------------------------------------------
__global__ __launch_bounds__(256, 1)
void proj_qk_kernel(const float* __restrict__ xs,
                    const float* __restrict__ wq, const float* __restrict__ bq,
                    const float* __restrict__ wk, const float* __restrict__ bk)
{
    const float* W  = blockIdx.z ? wk : wq;
    const float* bb = blockIdx.z ? bk : bq;
    float* out      = blockIdx.z ? g_k : g_q;
    gemm_mma(xs, HDIM, W, HDIM, out, EDIM, bb, 1, 1.0f,
             blockIdx.y * 128, blockIdx.x * 128, HDIM / 32);
}

// Vt[e][b*S+s] = WV[e,:] . xs[b*S+s,:] + bv[e]
__global__ __launch_bounds__(256, 1)
void proj_vt_kernel(const float* __restrict__ xs,
                    const float* __restrict__ wv, const float* __restrict__ bv)
{
    gemm_mma(wv, HDIM, xs, HDIM, g_vt, (size_t)BATCH * SEQ, bv, 2, 1.0f,
             blockIdx.y * 128, blockIdx.x * 128, HDIM / 32);
}

__global__ __launch_bounds__(256, 1)
void qkt_kernel()
{
    if (blockIdx.x > blockIdx.y) return;   // strictly above diagonal: never read
    const int b = blockIdx.z;
    gemm_mma(g_q + (size_t)b * SEQ * EDIM, EDIM,
             g_k + (size_t)b * SEQ * EDIM, EDIM,
             g_p + (size_t)b * SEQ * SEQ,  SEQ,
             nullptr, 0, 0.03125f, blockIdx.y * 128, blockIdx.x * 128, EDIM / 32);
}

__global__ __launch_bounds__(256, 1)
void pv_kernel(float* __restrict__ out)
{
    const int b = blockIdx.z;
    const int nchunks = (blockIdx.y + 1) * 4;   // K bound = (y+1)*128 cols of P
    gemm_mma(g_p + (size_t)b * SEQ * SEQ, SEQ,
             g_vt + (size_t)b * SEQ,      (size_t)BATCH * SEQ,
             out + (size_t)b * SEQ * EDIM, EDIM,
             nullptr, 0, 1.0f, blockIdx.y * 128, blockIdx.x * 128, nchunks);
}

// ---------------------------------------------------------------------------
// fp32 causal row softmax
// ---------------------------------------------------------------------------
__global__ __launch_bounds__(256) void softmax_kernel()
{
    const int m = blockIdx.x, b = blockIdx.y;
    float* row = g_p + (size_t)b * SEQ * SEQ + (size_t)m * SEQ;
    const int nv = m + 1;
    const int tid = threadIdx.x;
    __shared__ float red[8];

    float mx = -3.4e38f;
    for (int n = tid; n < nv; n += 256) mx = fmaxf(mx, row[n]);
    #pragma unroll
    for (int o = 16; o; o >>= 1) mx = fmaxf(mx, __shfl_xor_sync(0xffffffffu, mx, o));
    if ((tid & 31) == 0) red[tid >> 5] = mx;
    __syncthreads();
    float mall = red[0];
    #pragma unroll
    for (int i = 1; i < 8; i++) mall = fmaxf(mall, red[i]);
    __syncthreads();

    float s = 0.f;
    for (int n = tid; n < nv; n += 256) s += __expf(row[n] - mall);
    #pragma unroll
    for (int o = 16; o; o >>= 1) s += __shfl_xor_sync(0xffffffffu, s, o);
    if ((tid & 31) == 0) red[tid >> 5] = s;
    __syncthreads();
    float tot = 0.f;
    #pragma unroll
    for (int i = 0; i < 8; i++) tot += red[i];
    const float inv = 1.0f / tot;

    for (int n = tid; n < SEQ; n += 256)
        row[n] = (n < nv) ? __expf(row[n] - mall) * inv : 0.f;
}

// ---------------------------------------------------------------------------
extern "C" void kernel_launch(void* const* d_in, const int* in_sizes, int n_in,
                              void* d_out, int out_size)
{
    const float* xs   = (const float*)d_in[0];
    const float* WQ_w = (const float*)d_in[1];
    const float* WQ_b = (const float*)d_in[2];
    const float* WK_w = (const float*)d_in[3];
    const float* WK_b = (const float*)d_in[4];
    const float* WV_w = (const float*)d_in[5];
    const float* WV_b = (const float*)d_in[6];
    float* out = (float*)d_out;

    cudaFuncSetAttribute(proj_qk_kernel, cudaFuncAttributeMaxDynamicSharedMemorySize, SMEM_BYTES);
    cudaFuncSetAttribute(proj_vt_kernel, cudaFuncAttributeMaxDynamicSharedMemorySize, SMEM_BYTES);
    cudaFuncSetAttribute(qkt_kernel,     cudaFuncAttributeMaxDynamicSharedMemorySize, SMEM_BYTES);
    cudaFuncSetAttribute(pv_kernel,      cudaFuncAttributeMaxDynamicSharedMemorySize, SMEM_BYTES);

    proj_qk_kernel<<<dim3(EDIM / 128, (BATCH * SEQ) / 128, 2), 256, SMEM_BYTES>>>(
        xs, WQ_w, WQ_b, WK_w, WK_b);
    proj_vt_kernel<<<dim3((BATCH * SEQ) / 128, EDIM / 128, 1), 256, SMEM_BYTES>>>(
        xs, WV_w, WV_b);
    qkt_kernel<<<dim3(SEQ / 128, SEQ / 128, BATCH), 256, SMEM_BYTES>>>();
    softmax_kernel<<<dim3(SEQ, BATCH), 256>>>();
    pv_kernel<<<dim3(EDIM / 128, SEQ / 128, BATCH), 256, SMEM_BYTES>>>(out);
}